// round 3
// baseline (speedup 1.0000x reference)
#include <cuda_runtime.h>
#include <cuda_bf16.h>

#define NCLS 10
#define NBINS (NCLS + 1)   // bin 10 = dummy for invalid pixels
#define TPB 256
#define MAXBLK 1280

// Per-block partials (each block overwrites its own slot every replay — no
// zeroing pass needed). Layout [class][block] so the last-block reduce loads
// are coalesced along the block axis.
__device__ float g_psum[NCLS][MAXBLK];
__device__ float g_pcnt[NCLS][MAXBLK];
// Arrival counter for the threadfence-reduction pattern. Starts at 0 at module
// load; the last block resets it to 0 after use, so graph replays are
// deterministic.
__device__ unsigned int g_count = 0;

__global__ void __launch_bounds__(TPB) loss_kernel(
    const float4* __restrict__ out4,
    const float4* __restrict__ tgt4,
    const int4*   __restrict__ msk4,
    float* __restrict__ out,
    int n4)
{
    // Per-thread privatized class bins: bins[class][tid] as float2{sum,count}.
    // tid-major => conflict-free 64-bit shared accesses, zero contention.
    __shared__ float2 bins[NBINS * TPB];
    __shared__ int s_is_last;
    const int tid = threadIdx.x;
    const int nblk = gridDim.x;

    #pragma unroll
    for (int c = 0; c < NBINS; c++)
        bins[c * TPB + tid] = make_float2(0.0f, 0.0f);
    __syncthreads();

    const int stride = nblk * TPB;
    for (int i = blockIdx.x * TPB + tid; i < n4; i += stride) {
        float4 o = out4[i];
        float4 t = tgt4[i];
        int4   m = msk4[i];

        float d0 = o.x - t.x, d1 = o.y - t.y, d2 = o.z - t.z, d3 = o.w - t.w;
        float s0 = d0 * d0, s1 = d1 * d1, s2 = d2 * d2, s3 = d3 * d3;
        // targets hold exact integers 0..9 as floats
        int c0 = (m.x == 1) ? (int)t.x : NCLS;
        int c1 = (m.y == 1) ? (int)t.y : NCLS;
        int c2 = (m.z == 1) ? (int)t.z : NCLS;
        int c3 = (m.w == 1) ? (int)t.w : NCLS;

        float2* p;
        float2 v;
        p = &bins[c0 * TPB + tid]; v = *p; v.x += s0; v.y += 1.0f; *p = v;
        p = &bins[c1 * TPB + tid]; v = *p; v.x += s1; v.y += 1.0f; *p = v;
        p = &bins[c2 * TPB + tid]; v = *p; v.x += s2; v.y += 1.0f; *p = v;
        p = &bins[c3 * TPB + tid]; v = *p; v.x += s3; v.y += 1.0f; *p = v;
    }
    __syncthreads();

    // Intra-block tree reduce over the 256 per-thread bins (dummy bin dropped).
    for (int s = TPB / 2; s > 0; s >>= 1) {
        if (tid < s) {
            #pragma unroll
            for (int c = 0; c < NCLS; c++) {
                float2 a = bins[c * TPB + tid];
                float2 b = bins[c * TPB + tid + s];
                bins[c * TPB + tid] = make_float2(a.x + b.x, a.y + b.y);
            }
        }
        __syncthreads();
    }

    // Publish per-block partials.
    if (tid < NCLS) {
        g_psum[tid][blockIdx.x] = bins[tid * TPB].x;
        g_pcnt[tid][blockIdx.x] = bins[tid * TPB].y;
    }
    __threadfence();  // make partials visible before signaling arrival

    if (tid == 0) {
        unsigned int prev = atomicAdd(&g_count, 1u);
        s_is_last = (prev == (unsigned int)(nblk - 1));
    }
    __syncthreads();
    if (!s_is_last) return;

    // ── Last block: reduce all per-block partials and finalize ──
    float sacc[NCLS], cacc[NCLS];
    #pragma unroll
    for (int c = 0; c < NCLS; c++) { sacc[c] = 0.0f; cacc[c] = 0.0f; }
    for (int b = tid; b < nblk; b += TPB) {
        #pragma unroll
        for (int c = 0; c < NCLS; c++) {
            sacc[c] += g_psum[c][b];
            cacc[c] += g_pcnt[c][b];
        }
    }
    #pragma unroll
    for (int c = 0; c < NCLS; c++)
        bins[c * TPB + tid] = make_float2(sacc[c], cacc[c]);
    __syncthreads();

    for (int s = TPB / 2; s > 0; s >>= 1) {
        if (tid < s) {
            #pragma unroll
            for (int c = 0; c < NCLS; c++) {
                float2 a = bins[c * TPB + tid];
                float2 b = bins[c * TPB + tid + s];
                bins[c * TPB + tid] = make_float2(a.x + b.x, a.y + b.y);
            }
        }
        __syncthreads();
    }

    // Output layout: [loss(1), loss_each(10), class_n(10)] = 21 floats
    float le = 0.0f;
    if (tid < NCLS) {
        float sum = bins[tid * TPB].x;
        float n   = bins[tid * TPB].y;
        le = (n > 0.0f) ? (sum / fmaxf(n, 1.0f)) : 0.0f;
        out[1 + tid]        = le;
        out[1 + NCLS + tid] = n;
    }
    if (tid == 0)
        g_count = 0;  // reset for next graph replay (all blocks have arrived)
    if (tid < 32) {
        float w = 0.1f * le;
        #pragma unroll
        for (int s = 16; s > 0; s >>= 1)
            w += __shfl_down_sync(0xffffffffu, w, s);
        if (tid == 0)
            out[0] = w;
    }
}

extern "C" void kernel_launch(void* const* d_in, const int* in_sizes, int n_in,
                              void* d_out, int out_size) {
    const float4* o4 = (const float4*)d_in[0];
    const float4* t4 = (const float4*)d_in[1];
    const int4*   m4 = (const int4*)d_in[2];
    float* out = (float*)d_out;

    int n  = in_sizes[0];      // 16,777,216 — divisible by 4
    int n4 = n >> 2;

    int blocks = 148 * 8;      // one full wave (threads-limited occupancy = 8/SM)
    int maxb = (n4 + TPB - 1) / TPB;
    if (blocks > maxb) blocks = maxb;
    if (blocks > MAXBLK) blocks = MAXBLK;
    if (blocks < 1) blocks = 1;

    loss_kernel<<<blocks, TPB>>>(o4, t4, m4, out, n4);
}